// round 13
// baseline (speedup 1.0000x reference)
#include <cuda_runtime.h>
#include <cuda_fp16.h>
#include <math.h>
#include <stdint.h>

#define BATCH 4
#define RAYS  8192
#define NRAYS (BATCH*RAYS)          // 32768
#define NS    48
#define RES   48
#define CH    32
#define NPTS  (NRAYS*NS)            // 1572864
#define NTILES (NPTS/128)           // 12288

#define DT    0.03125f

// ---------------- device scratch ----------------
__device__ __align__(16) __half g_mat_h[3*BATCH*RES*RES*CH];
__device__ __align__(16) __half g_vec_h[3*BATCH*RES*CH];
__device__ __align__(16) float  g_rgb[(size_t)NPTS*3];
__device__ __align__(16) float  g_bias[(size_t)NRAYS*64];
__device__ unsigned g_c0 = 0, g_c1 = 0, g_c2 = 0;

__device__ __forceinline__ float tanh_apx(float x) {
    float r;
    asm("tanh.approx.f32 %0, %1;" : "=f"(r) : "f"(x));
    return r;
}

__device__ __forceinline__ float gelu_fast(float x) {
    float inner = 0.7978845608f * x * fmaf(0.044715f * x, x, 1.0f);
    return 0.5f * x * (1.0f + tanh_apx(inner));
}

__device__ __forceinline__ float sigmoid_fast(float x) {
    return 0.5f * (1.0f + tanh_apx(0.5f * x));
}

__device__ __forceinline__ __half2 gelu_h2(__half2 x) {
    const __half2 K2  = __float2half2_rn(0.035677408f);
    const __half2 K0  = __float2half2_rn(0.7978845608f);
    const __half2 H05 = __float2half2_rn(0.5f);
    __half2 x2 = __hmul2(x, x);
    __half2 inner = __hmul2(x, __hfma2(x2, K2, K0));
    uint32_t ti;
    asm("tanh.approx.f16x2 %0, %1;" : "=r"(ti) : "r"(*(uint32_t*)&inner));
    __half2 th = *(__half2*)&ti;
    __half2 h = __hmul2(x, H05);
    return __hfma2(h, th, h);
}

__device__ __forceinline__ void mma_f16(float d[4],
                                        uint32_t a0, uint32_t a1, uint32_t a2, uint32_t a3,
                                        uint32_t b0, uint32_t b1) {
    asm volatile("mma.sync.aligned.m16n8k16.row.col.f32.f16.f16.f32 "
                 "{%0,%1,%2,%3}, {%4,%5,%6,%7}, {%8,%9}, {%0,%1,%2,%3};"
                 : "+f"(d[0]), "+f"(d[1]), "+f"(d[2]), "+f"(d[3])
                 : "r"(a0), "r"(a1), "r"(a2), "r"(a3), "r"(b0), "r"(b1));
}

__device__ __forceinline__ void ldsm_x4(uint32_t& r0, uint32_t& r1, uint32_t& r2, uint32_t& r3,
                                        uint32_t saddr) {
    asm volatile("ldmatrix.sync.aligned.m8n8.x4.shared.b16 {%0,%1,%2,%3}, [%4];"
                 : "=r"(r0), "=r"(r1), "=r"(r2), "=r"(r3) : "r"(saddr));
}

__device__ __forceinline__ uint32_t pack_h2(float lo, float hi) {
    __half2 h = __floats2half2_rn(lo, hi);
    return *(uint32_t*)&h;
}

// software grid barrier — all blocks are co-resident (launch_bounds(256,2), grid=2*NSM)
__device__ __forceinline__ void gbar(unsigned* c, unsigned nb) {
    __syncthreads();
    if (threadIdx.x == 0) {
        __threadfence();
        atomicAdd(c, 1u);
        while (atomicAdd(c, 0u) < nb) __nanosleep(64);
        __threadfence();
    }
    __syncthreads();
}

// ---------------- megakernel: prep -> barrier -> tiles -> barrier -> render ------
#define F_PITCH 88
#define F_BUF_FLOATS (128*F_PITCH/2)      // 5632
#define F_BUF_BYTES  (F_BUF_FLOATS*4)     // 22528
#define OF_B1   (2*F_BUF_FLOATS)          // 11264
#define OF_B2   (OF_B1 + 5*4*136)         // +2720 -> 13984
#define OF_W2   (OF_B2 + 4*4*136)         // +2176 -> 16160
#define OF_BM   (OF_W2 + 192)             // 16352
#define OF_BIAS (OF_BM + 64)              // 16416, 2 x 256 floats
#define SMEM_FLOATS (OF_BIAS + 512)       // 16928 floats = 67712 B

__global__ __launch_bounds__(256, 2)
void k_mega(const float* __restrict__ rays_o, const float* __restrict__ rays_d,
            const float* __restrict__ matrixs, const float* __restrict__ vectors,
            const float* __restrict__ w_mat, const float* __restrict__ b_mat,
            const float* __restrict__ w1, const float* __restrict__ b1,
            const float* __restrict__ w2, const float* __restrict__ b2,
            float* __restrict__ out_rgb, float* __restrict__ out_depth,
            float* __restrict__ out_sigma) {
    extern __shared__ float sm[];
    float* sB1   = sm + OF_B1;
    float* sB2   = sm + OF_B2;
    float* sW2   = sm + OF_W2;
    float* sBm   = sm + OF_BM;
    float* sBias = sm + OF_BIAS;

    const int tid  = threadIdx.x;
    const int lane = tid & 31;
    const int wid  = tid >> 5;
    const int q    = lane & 3;
    const int g    = lane >> 2;
    const unsigned nb = gridDim.x;
    const int gtid    = blockIdx.x * 256 + tid;
    const int gstride = nb * 256;

    // ---- per-block smem init: zero F pads + weight packing ----
    {
        int bufr = tid >> 7, row = tid & 127;
        *(uint4*)((__half*)sm + bufr*F_BUF_FLOATS*2 + row*F_PITCH + 72) = make_uint4(0,0,0,0);
    }
    for (int i = tid; i < 5*4*64; i += 256) {
        int kb = i >> 8, qq = (i >> 6) & 3, n = i & 63;
        int k0 = kb*16 + 2*qq;
        float v0 = w_mat[k0*64 + n];
        float v1 = w_mat[(k0+1)*64 + n];
        float v2 = (k0+8 < 72) ? w_mat[(k0+8)*64 + n] : 0.0f;
        float v3 = (k0+9 < 72) ? w_mat[(k0+9)*64 + n] : 0.0f;
        uint2 e;
        e.x = pack_h2(v0, v1);
        e.y = pack_h2(v2, v3);
        *(uint2*)(sB1 + (kb*4 + qq)*136 + n*2) = e;
    }
    for (int i = tid; i < 4*4*64; i += 256) {
        int kb = i >> 8, qq = (i >> 6) & 3, n = i & 63;
        int k0 = kb*16 + 2*qq;
        uint2 e;
        e.x = pack_h2(w1[k0*64 + n],     w1[(k0+1)*64 + n]);
        e.y = pack_h2(w1[(k0+8)*64 + n], w1[(k0+9)*64 + n]);
        *(uint2*)(sB2 + (kb*4 + qq)*136 + n*2) = e;
    }
    if (tid < 192) sW2[tid] = w2[tid];
    if (tid < 64)  sBm[tid] = b_mat[tid];

    // ---- phase 0: global prep (grid-strided) ----
    for (int idx = gtid; idx < 3*BATCH*RES*RES*CH; idx += gstride) {
        int c   = idx % CH;
        int pix = (idx / CH) % (RES*RES);
        int ib  = idx / (CH*RES*RES);
        g_mat_h[idx] = __float2half_rn(matrixs[((size_t)ib*CH + c)*(RES*RES) + pix]);
    }
    for (int idx = gtid; idx < 3*BATCH*RES*CH; idx += gstride) {
        int c  = idx % CH;
        int r  = (idx / CH) % RES;
        int ib = idx / (CH*RES);
        g_vec_h[idx] = __float2half_rn(vectors[((size_t)ib*CH + c)*RES + r]);
    }
    for (int r = gtid; r < NRAYS; r += gstride) {
        float dx = rays_d[r*3+0], dy = rays_d[r*3+1], dz = rays_d[r*3+2];
        float inv = 1.0f / sqrtf(dx*dx + dy*dy + dz*dz);
        dx *= inv; dy *= inv; dz *= inv;
        float pe[27];
        pe[0] = dx; pe[1] = dy; pe[2] = dz;
        float f = 1.0f;
        #pragma unroll
        for (int fi = 0; fi < 4; fi++) {
            float s, c;
            sincosf(dx*f, &s, &c); pe[3 + fi*3 + 0] = s; pe[15 + fi*3 + 0] = c;
            sincosf(dy*f, &s, &c); pe[3 + fi*3 + 1] = s; pe[15 + fi*3 + 1] = c;
            sincosf(dz*f, &s, &c); pe[3 + fi*3 + 2] = s; pe[15 + fi*3 + 2] = c;
            f *= 2.0f;
        }
        // j-blocked (2x32) to stay under the 128-reg cap
        #pragma unroll 1
        for (int jb = 0; jb < 2; jb++) {
            float acc[32];
            #pragma unroll
            for (int j = 0; j < 32; j++) acc[j] = b1[jb*32 + j];
            #pragma unroll 1
            for (int k = 0; k < 27; k++) {
                float v = pe[k];
                const float* wr = w1 + (64 + k)*64 + jb*32;
                #pragma unroll
                for (int j = 0; j < 32; j++) acc[j] += v * wr[j];
            }
            float* o = g_bias + (size_t)r*64 + jb*32;
            #pragma unroll
            for (int j = 0; j < 32; j++) o[j] = acc[j];
        }
    }
    gbar(&g_c0, nb);

    const int m0 = wid * 16;
    const int lp   = tid >> 1;
    const int csel = tid & 1;

    const uint32_t sF_sh0 = (uint32_t)__cvta_generic_to_shared((__half*)sm);
    const uint32_t a_base0 = sF_sh0 +
        (uint32_t)(((m0 + (lane & 15)) * F_PITCH + ((lane >> 4) * 8)) * 2);

    int buf = 0;
    #pragma unroll 1
    for (int tile = blockIdx.x; tile < NTILES; tile += nb, buf ^= 1) {
        const int pbase = tile * 128;
        __half* sF     = (__half*)sm + buf * F_BUF_FLOATS * 2;
        float*  sBiasB = sBias + buf * 256;
        const int ray0 = pbase / NS;

        // ---- stage per-ray bias (<=4 rays per 128-pt tile) ----
        {
            int row = tid >> 6, col = tid & 63;
            int r = ray0 + row;
            if (r > NRAYS-1) r = NRAYS-1;
            sBiasB[row*64 + col] = g_bias[(size_t)r*64 + col];
        }

        // ================= sampling phase: 2 adjacent threads per point ========
        {
            const int p   = pbase + lp;
            const int s   = p % NS;
            const int ray = p / NS;
            const int b   = ray / RAYS;

            const float ox = rays_o[ray*3+0], oy = rays_o[ray*3+1], oz = rays_o[ray*3+2];
            const float dx = rays_d[ray*3+0], dy = rays_d[ray*3+1], dz = rays_d[ray*3+2];
            const float t  = ((float)s + 0.5f) * DT;

            const float px = ((ox + dx*t) + 0.8f) * 1.25f - 1.0f;
            const float py = ((oy + dy*t) + 0.8f) * 1.25f - 1.0f;
            const float pz = ((oz + dz*t) + 0.8f) * 1.25f - 1.0f;

            float sigma = 0.0f;
            __half* fo = sF + lp*F_PITCH;
            const int cc0 = csel*2;

            #pragma unroll 1
            for (int pl = 0; pl < 3; pl++) {
                const float cx = (pl == 0) ? px : ((pl == 1) ? pz : py);
                const float cy = (pl == 0) ? py : ((pl == 1) ? px : pz);
                const float cz = (pl == 0) ? pz : ((pl == 1) ? py : px);

                const float fx = (cx + 1.0f) * 23.5f;
                const float fy = (cy + 1.0f) * 23.5f;
                const float fz = (cz + 1.0f) * 23.5f;
                const float x0f = floorf(fx), y0f = floorf(fy), z0f = floorf(fz);
                const float wx = fx - x0f, wy = fy - y0f, wz = fz - z0f;
                const int ix0 = (int)x0f, iy0 = (int)y0f, iz0 = (int)z0f;

                const float mx0 = (ix0 >= 0  && ix0 <  RES)   ? 1.0f : 0.0f;
                const float mx1 = (ix0 >= -1 && ix0 <  RES-1) ? 1.0f : 0.0f;
                const float my0 = (iy0 >= 0  && iy0 <  RES)   ? 1.0f : 0.0f;
                const float my1 = (iy0 >= -1 && iy0 <  RES-1) ? 1.0f : 0.0f;
                const float mz0 = (iz0 >= 0  && iz0 <  RES)   ? 1.0f : 0.0f;
                const float mz1 = (iz0 >= -1 && iz0 <  RES-1) ? 1.0f : 0.0f;

                const int cx0 = min(max(ix0,   0), RES-1), cx1 = min(max(ix0+1, 0), RES-1);
                const int cy0 = min(max(iy0,   0), RES-1), cy1 = min(max(iy0+1, 0), RES-1);
                const int cz0 = min(max(iz0,   0), RES-1), cz1 = min(max(iz0+1, 0), RES-1);

                const float w00 = (1.0f-wx)*(1.0f-wy)*mx0*my0;
                const float w10 = wx*(1.0f-wy)*mx1*my0;
                const float w01 = (1.0f-wx)*wy*mx0*my1;
                const float w11 = wx*wy*mx1*my1;
                const float u0  = (1.0f-wz)*mz0;
                const float u1  = wz*mz1;

                const __half* mb = g_mat_h + ((size_t)(pl*BATCH + b) * (RES*RES)) * CH;
                const __half* vb = g_vec_h + ((size_t)(pl*BATCH + b) * RES) * CH;
                const uint4* p00 = (const uint4*)(mb + (size_t)(cy0*RES + cx0) * CH);
                const uint4* p10 = (const uint4*)(mb + (size_t)(cy0*RES + cx1) * CH);
                const uint4* p01 = (const uint4*)(mb + (size_t)(cy1*RES + cx0) * CH);
                const uint4* p11 = (const uint4*)(mb + (size_t)(cy1*RES + cx1) * CH);
                const uint4* q0  = (const uint4*)(vb + (size_t)cz0 * CH);
                const uint4* q1  = (const uint4*)(vb + (size_t)cz1 * CH);

                const __half2 W00 = __float2half2_rn(w00);
                const __half2 W10 = __float2half2_rn(w10);
                const __half2 W01 = __float2half2_rn(w01);
                const __half2 W11 = __float2half2_rn(w11);
                const __half2 U0  = __float2half2_rn(u0);
                const __half2 U1  = __float2half2_rn(u1);

                #pragma unroll
                for (int ci = 0; ci < 2; ci++) {
                    const int cc = cc0 + ci;
                    uint4 ua = p00[cc], ub = p10[cc], uc = p01[cc], ud = p11[cc];
                    uint4 ue = q0[cc],  uf = q1[cc];
                    const __half2* ha = (const __half2*)&ua;
                    const __half2* hb = (const __half2*)&ub;
                    const __half2* hc = (const __half2*)&uc;
                    const __half2* hd = (const __half2*)&ud;
                    const __half2* he = (const __half2*)&ue;
                    const __half2* hf = (const __half2*)&uf;
                    if (cc == 0) {
                        #pragma unroll
                        for (int j = 0; j < 4; j++) {
                            float2 fa = __half22float2(ha[j]);
                            float2 fb = __half22float2(hb[j]);
                            float2 fc = __half22float2(hc[j]);
                            float2 fd = __half22float2(hd[j]);
                            float2 fe = __half22float2(he[j]);
                            float2 ff = __half22float2(hf[j]);
                            float pf0 = w00*fa.x + w10*fb.x + w01*fc.x + w11*fd.x;
                            float pf1 = w00*fa.y + w10*fb.y + w01*fc.y + w11*fd.y;
                            float lf0 = u0*fe.x + u1*ff.x;
                            float lf1 = u0*fe.y + u1*ff.y;
                            sigma += pf0*lf0 + pf1*lf1;
                        }
                    } else {
                        uint4 packed;
                        uint32_t* pk = &packed.x;
                        #pragma unroll
                        for (int j = 0; j < 4; j++) {
                            __half2 pf = __hmul2(hd[j], W11);
                            pf = __hfma2(hc[j], W01, pf);
                            pf = __hfma2(hb[j], W10, pf);
                            pf = __hfma2(ha[j], W00, pf);
                            __half2 lf = __hmul2(hf[j], U1);
                            lf = __hfma2(he[j], U0, lf);
                            __half2 gv = gelu_h2(__hmul2(pf, lf));
                            pk[j] = *(uint32_t*)&gv;
                        }
                        *(uint4*)(fo + pl*24 + (cc-1)*8) = packed;
                    }
                }
            }
            if (csel == 0) out_sigma[p] = fmaxf(sigma, 0.0f);
        }
        __syncthreads();

        const uint32_t a_base = a_base0 + buf * F_BUF_BYTES;

        // ================= GEMM1 =================
        float acc[8][4];
        #pragma unroll
        for (int nbb = 0; nbb < 8; nbb++) {
            float bv0 = sBm[nbb*8 + 2*q];
            float bv1 = sBm[nbb*8 + 2*q + 1];
            acc[nbb][0] = bv0; acc[nbb][1] = bv1; acc[nbb][2] = bv0; acc[nbb][3] = bv1;
        }
        #pragma unroll 1
        for (int kb = 0; kb < 5; kb++) {
            uint32_t a0, a1, a2, a3;
            ldsm_x4(a0, a1, a2, a3, a_base + kb*32);
            const float* brow = sB1 + (kb*4 + q)*136 + g*2;
            #pragma unroll
            for (int nbb = 0; nbb < 8; nbb++) {
                uint2 bv = *(const uint2*)(brow + nbb*16);
                mma_f16(acc[nbb], a0, a1, a2, a3, bv.x, bv.y);
            }
        }
        __syncwarp();
        #pragma unroll
        for (int nbb = 0; nbb < 8; nbb++) {
            int c0 = nbb*8 + 2*q;
            __half2* dA = (__half2*)(sF + (m0 + g)*F_PITCH + c0);
            __half2* dB = (__half2*)(sF + (m0 + g + 8)*F_PITCH + c0);
            *dA = gelu_h2(__floats2half2_rn(acc[nbb][0], acc[nbb][1]));
            *dB = gelu_h2(__floats2half2_rn(acc[nbb][2], acc[nbb][3]));
        }
        __syncwarp();
        // ================= GEMM2 =================
        float acc2[8][4];
        #pragma unroll
        for (int nbb = 0; nbb < 8; nbb++)
            acc2[nbb][0] = acc2[nbb][1] = acc2[nbb][2] = acc2[nbb][3] = 0.0f;
        #pragma unroll 1
        for (int kb = 0; kb < 4; kb++) {
            uint32_t a0, a1, a2, a3;
            ldsm_x4(a0, a1, a2, a3, a_base + kb*32);
            const float* brow = sB2 + (kb*4 + q)*136 + g*2;
            #pragma unroll
            for (int nbb = 0; nbb < 8; nbb++) {
                uint2 bv = *(const uint2*)(brow + nbb*16);
                mma_f16(acc2[nbb], a0, a1, a2, a3, bv.x, bv.y);
            }
        }
        // ---- epilogue 2 ----
        const int pA = pbase + m0 + g;
        const int pB = pA + 8;
        const float* biasA = sBiasB + (pA / NS - ray0) * 64;
        const float* biasB = sBiasB + (pB / NS - ray0) * 64;
        float rA0 = 0.f, rA1 = 0.f, rA2 = 0.f, rB0 = 0.f, rB1 = 0.f, rB2 = 0.f;
        #pragma unroll
        for (int nbb = 0; nbb < 8; nbb++) {
            int c0 = nbb*8 + 2*q, c1 = c0 + 1;
            float v00 = gelu_fast(acc2[nbb][0] + biasA[c0]);
            float v01 = gelu_fast(acc2[nbb][1] + biasA[c1]);
            float v10 = gelu_fast(acc2[nbb][2] + biasB[c0]);
            float v11 = gelu_fast(acc2[nbb][3] + biasB[c1]);
            float w00 = sW2[c0*3+0], w01 = sW2[c0*3+1], w02 = sW2[c0*3+2];
            float w10 = sW2[c1*3+0], w11 = sW2[c1*3+1], w12 = sW2[c1*3+2];
            rA0 += v00*w00 + v01*w10;
            rA1 += v00*w01 + v01*w11;
            rA2 += v00*w02 + v01*w12;
            rB0 += v10*w00 + v11*w10;
            rB1 += v10*w01 + v11*w11;
            rB2 += v10*w02 + v11*w12;
        }
        #pragma unroll
        for (int off = 1; off <= 2; off <<= 1) {
            rA0 += __shfl_xor_sync(0xffffffffu, rA0, off);
            rA1 += __shfl_xor_sync(0xffffffffu, rA1, off);
            rA2 += __shfl_xor_sync(0xffffffffu, rA2, off);
            rB0 += __shfl_xor_sync(0xffffffffu, rB0, off);
            rB1 += __shfl_xor_sync(0xffffffffu, rB1, off);
            rB2 += __shfl_xor_sync(0xffffffffu, rB2, off);
        }
        if (q == 0) {
            float c0 = b2[0], c1 = b2[1], c2 = b2[2];
            float* oA = g_rgb + (size_t)pA * 3;
            oA[0] = sigmoid_fast(rA0 + c0);
            oA[1] = sigmoid_fast(rA1 + c1);
            oA[2] = sigmoid_fast(rA2 + c2);
            float* oB = g_rgb + (size_t)pB * 3;
            oB[0] = sigmoid_fast(rB0 + c0);
            oB[1] = sigmoid_fast(rB1 + c1);
            oB[2] = sigmoid_fast(rB2 + c2);
        }
        // no trailing sync: next tile samples into the other buffer
    }

    gbar(&g_c1, nb);

    // ---- phase 2: per-ray compositing ----
    for (int r = gtid; r < NRAYS; r += gstride) {
        float T = 1.0f, a0 = 0.0f, a1 = 0.0f, a2 = 0.0f, dep = 0.0f;
        const float* rp = g_rgb + (size_t)r * NS * 3;
        float* wp = out_sigma + (size_t)r * NS;
        #pragma unroll 1
        for (int s = 0; s < NS; s++) {
            float sg = wp[s];
            float al = 1.0f - __expf(-sg * DT);
            float wt = al * T;
            T *= (1.0f - al + 1e-10f);
            wp[s] = wt;
            dep += wt * (((float)s + 0.5f) * DT);
            a0 += wt * rp[s*3+0];
            a1 += wt * rp[s*3+1];
            a2 += wt * rp[s*3+2];
        }
        out_rgb[r*3+0] = a0;
        out_rgb[r*3+1] = a1;
        out_rgb[r*3+2] = a2;
        out_depth[r]   = dep;
    }

    // ---- reset barrier counters for the next graph replay ----
    __syncthreads();
    if (tid == 0) {
        __threadfence();
        if (atomicAdd(&g_c2, 1u) == nb - 1) {
            atomicExch(&g_c0, 0u);
            atomicExch(&g_c1, 0u);
            atomicExch(&g_c2, 0u);
        }
    }
}

// ---------------- launch ----------------
extern "C" void kernel_launch(void* const* d_in, const int* in_sizes, int n_in,
                              void* d_out, int out_size) {
    const float* rays_o  = (const float*)d_in[0];
    const float* rays_d  = (const float*)d_in[1];
    const float* matrixs = (const float*)d_in[2];
    const float* vectors = (const float*)d_in[3];
    const float* w_mat   = (const float*)d_in[4];
    const float* b_mat   = (const float*)d_in[5];
    const float* w1      = (const float*)d_in[6];
    const float* b1      = (const float*)d_in[7];
    const float* w2      = (const float*)d_in[8];
    const float* b2      = (const float*)d_in[9];

    float* out       = (float*)d_out;
    float* out_rgb   = out;
    float* out_depth = out + NRAYS*3;
    float* out_w     = out + NRAYS*4;

    static int nsm = 0;
    if (nsm == 0) {
        cudaDeviceProp prop;
        cudaGetDeviceProperties(&prop, 0);
        nsm = prop.multiProcessorCount;
        cudaFuncSetAttribute(k_mega, cudaFuncAttributeMaxDynamicSharedMemorySize,
                             SMEM_FLOATS * sizeof(float));
    }

    k_mega<<<2*nsm, 256, SMEM_FLOATS * sizeof(float)>>>(
        rays_o, rays_d, matrixs, vectors, w_mat, b_mat, w1, b1, w2, b2,
        out_rgb, out_depth, out_w);
}